// round 8
// baseline (speedup 1.0000x reference)
#include <cuda_runtime.h>
#include <cuda_bf16.h>

#define NN 50000
#define EE 300000
#define ETOT (EE + NN)          // edges + self loops
#define NEG_SLOPE 0.2f
#define EPS 1e-16f
#define SCAN_B 512
#define NBLK ((NN + SCAN_B - 1) / SCAN_B)   // 98
#define NCONV ((ETOT + 255) / 256)          // 1368 convert blocks

typedef unsigned long long ull;

// ---------------- scratch (static device allocations only) ----------------
// INVARIANT: g_deg and g_pub are zero at every kernel_launch entry.
// (zero-initialized at load; re-zeroed at the start of k_agg2 each call)
__device__ int g_srcR[ETOT];
__device__ int g_dstR[ETOT];
__device__ int g_rank[ETOT];     // within-dst-segment rank (from atomic order)
__device__ int g_csr[ETOT];      // src ids sorted by dst
__device__ int g_deg[NN];
__device__ int g_rs[NN + 1];     // row starts
__device__ int g_pub[NBLK];      // lookback: (block aggregate + 1), 0 = unpublished

__device__ float g_h1[NN * 256];
__device__ float g_ssrc1[NN * 4];
__device__ float g_sdst1[NN * 4];
__device__ float g_out1[NN * 256];   // layer-1 ELU output

__device__ float g_h2[NN * 128];
__device__ float g_ssrc2[NN * 2];
__device__ float g_sdst2[NN * 2];

// ---------------- helpers ----------------
__device__ __forceinline__ float lrelu(float x) {
    return x > 0.f ? x : NEG_SLOPE * x;
}
__device__ __forceinline__ float elu(float x) {
    return x > 0.f ? x : expm1f(x);
}
__device__ __forceinline__ ull pack2(float a, float b) {
    ull r; asm("mov.b64 %0,{%1,%2};" : "=l"(r) : "f"(a), "f"(b)); return r;
}
__device__ __forceinline__ void unpack2(ull p, float& a, float& b) {
    asm("mov.b64 {%0,%1},%2;" : "=f"(a), "=f"(b) : "l"(p));
}
__device__ __forceinline__ ull fma2(ull a, ull b, ull c) {
    ull d; asm("fma.rn.f32x2 %0,%1,%2,%3;" : "=l"(d) : "l"(a), "l"(b), "l"(c));
    return d;
}

// ============ fused launch 0: edge convert (blocks < NCONV)  ================
// ============                 + GEMM1+scores1 (blocks >= NCONV) =============
// The two halves touch disjoint data (edge_index vs x/W1) and are independent;
// fusing them overlaps convert's latency-bound atomics under the GEMM.
__global__ void __launch_bounds__(256) k_conv_gemm1s(
        const void* __restrict__ ei,
        const float* __restrict__ x, const float* __restrict__ W1,
        const float* __restrict__ a_src1, const float* __restrict__ a_dst1) {
    __shared__ __align__(16) float sxt[27 * 16];   // transposed [k][m]
    __shared__ __align__(16) float sh1[16 * 256];  // h tile for scores
    int tid = threadIdx.x;

    if (blockIdx.x < NCONV) {
        // ---- edge convert + inline dtype detect + histogram + rank ----
        const int* ei32 = (const int*)ei;
        int probe = ei32[2 * tid + 1];
        int any = __syncthreads_or(probe);
        int is64 = (any == 0);

        int e = blockIdx.x * 256 + tid;
        if (e >= ETOT) return;
        int s, d;
        if (e >= EE) {                      // self loops
            s = d = e - EE;
        } else if (is64) {
            const long long* p = (const long long*)ei;
            s = (int)p[e]; d = (int)p[EE + e];
        } else {
            const int* p = (const int*)ei;
            s = p[e]; d = p[EE + e];
        }
        g_srcR[e] = s; g_dstR[e] = d;
        g_rank[e] = atomicAdd(&g_deg[d], 1);
        return;
    }

    // ---- GEMM1: [50000,27] @ [27,256] f32x2 packed, + scores1 ----
    int n0 = (blockIdx.x - NCONV) * 16;            // 50000 = 3125*16
    for (int i = tid; i < 27 * 16; i += 256) {
        int k = i >> 4, m = i & 15;
        sxt[i] = x[(n0 + m) * 27 + k];
    }
    float w[27];
#pragma unroll
    for (int k = 0; k < 27; k++) w[k] = W1[k * 256 + tid];
    __syncthreads();
    ull acc[8];
#pragma unroll
    for (int p = 0; p < 8; p++) acc[p] = 0ull;
#pragma unroll
    for (int k = 0; k < 27; k++) {
        ull wp = pack2(w[k], w[k]);
        const ulonglong2* xp = (const ulonglong2*)(sxt + k * 16);
#pragma unroll
        for (int q = 0; q < 4; q++) {
            ulonglong2 xv = xp[q];
            acc[2 * q]     = fma2(xv.x, wp, acc[2 * q]);
            acc[2 * q + 1] = fma2(xv.y, wp, acc[2 * q + 1]);
        }
    }
#pragma unroll
    for (int p = 0; p < 8; p++) {
        float lo, hi; unpack2(acc[p], lo, hi);
        g_h1[(size_t)(n0 + 2 * p) * 256 + tid] = lo;
        g_h1[(size_t)(n0 + 2 * p + 1) * 256 + tid] = hi;
        sh1[(2 * p) * 256 + tid] = lo;
        sh1[(2 * p + 1) * 256 + tid] = hi;
    }
    __syncthreads();

    // scores: 8 warps x 2 nodes. lane handles cols lane*4..+3 and 128+lane*4..
    // head = (lane<16 ? 0 : 1) for first group, (lane<16 ? 2 : 3) for second.
    int wrp = tid >> 5, lane = tid & 31;
    const float4* aS = (const float4*)a_src1;
    const float4* aD = (const float4*)a_dst1;
    float4 sA = aS[lane], sB = aS[32 + lane];
    float4 dA = aD[lane], dB = aD[32 + lane];
#pragma unroll
    for (int mi = 0; mi < 2; mi++) {
        int m = wrp * 2 + mi;
        const float4* hr = (const float4*)(sh1 + m * 256);
        float4 hA = hr[lane];
        float4 hB = hr[32 + lane];
        float psA = hA.x * sA.x + hA.y * sA.y + hA.z * sA.z + hA.w * sA.w;
        float pdA = hA.x * dA.x + hA.y * dA.y + hA.z * dA.z + hA.w * dA.w;
        float psB = hB.x * sB.x + hB.y * sB.y + hB.z * sB.z + hB.w * sB.w;
        float pdB = hB.x * dB.x + hB.y * dB.y + hB.z * dB.z + hB.w * dB.w;
#pragma unroll
        for (int o = 8; o; o >>= 1) {      // reduce within 16-lane halves
            psA += __shfl_down_sync(0xFFFFFFFFu, psA, o);
            pdA += __shfl_down_sync(0xFFFFFFFFu, pdA, o);
            psB += __shfl_down_sync(0xFFFFFFFFu, psB, o);
            pdB += __shfl_down_sync(0xFFFFFFFFu, pdB, o);
        }
        int n = n0 + m;
        if (lane == 0) {                   // heads 0, 2
            g_ssrc1[n * 4 + 0] = psA; g_sdst1[n * 4 + 0] = pdA;
            g_ssrc1[n * 4 + 2] = psB; g_sdst1[n * 4 + 2] = pdB;
        }
        if (lane == 16) {                  // heads 1, 3
            g_ssrc1[n * 4 + 1] = psA; g_sdst1[n * 4 + 1] = pdA;
            g_ssrc1[n * 4 + 3] = psB; g_sdst1[n * 4 + 3] = pdB;
        }
    }
}

// ---------------- single-pass exclusive scan (aggregate lookback) ----------
// 98 blocks, all resident simultaneously on 148 SMs -> safe to spin.
__global__ void __launch_bounds__(SCAN_B) k_scan() {
    __shared__ int sh[SCAN_B];
    __shared__ int s_sum;
    int b = blockIdx.x, t = threadIdx.x;
    int i = b * SCAN_B + t;
    int v = (i < NN) ? g_deg[i] : 0;
    sh[t] = v;
    __syncthreads();
#pragma unroll
    for (int d = 1; d < SCAN_B; d <<= 1) {
        int u = (t >= d) ? sh[t - d] : 0;
        __syncthreads();
        sh[t] += u;
        __syncthreads();
    }
    int excl = sh[t] - v;                 // block-local exclusive
    int agg = sh[SCAN_B - 1];             // block aggregate
    if (t == 0) {
        s_sum = 0;
        atomicExch(&g_pub[b], agg + 1);   // publish (write-through)
    }
    __syncthreads();
    if (t < b) {                          // sum predecessors' aggregates
        int p;
        do { p = *(volatile int*)&g_pub[t]; } while (p == 0);
        atomicAdd(&s_sum, p - 1);
    }
    __syncthreads();
    if (i < NN) g_rs[i] = excl + s_sum;
    if (b == NBLK - 1 && t == SCAN_B - 1) g_rs[NN] = ETOT;
}

// ---------------- scatter into CSR (no atomics) ----------------
__global__ void k_scatter() {
    int e = blockIdx.x * blockDim.x + threadIdx.x;
    if (e >= ETOT) return;
    int d = g_dstR[e];
    g_csr[g_rs[d] + g_rank[e]] = g_srcR[e];
}

// ---------------- layer-1 aggregation: warp / dst, atomic-free ----------------
__global__ void __launch_bounds__(256) k_agg1(const float* __restrict__ b1) {
    __shared__ __align__(16) float4 s_w4[8][32];
    __shared__ int s_si[8][32];
    int wid = (blockIdx.x * blockDim.x + threadIdx.x) >> 5;
    if (wid >= NN) return;
    int wip = threadIdx.x >> 5;
    int lane = threadIdx.x & 31;
    int rs = g_rs[wid], re = g_rs[wid + 1];
    float4 sd = *(const float4*)(g_sdst1 + wid * 4);

    // pass 1: per-head max
    float4 mx = make_float4(-3.4e38f, -3.4e38f, -3.4e38f, -3.4e38f);
    for (int j = rs + lane; j < re; j += 32) {
        int s = g_csr[j];
        float4 ss = *(const float4*)(g_ssrc1 + s * 4);
        mx.x = fmaxf(mx.x, lrelu(ss.x + sd.x));
        mx.y = fmaxf(mx.y, lrelu(ss.y + sd.y));
        mx.z = fmaxf(mx.z, lrelu(ss.z + sd.z));
        mx.w = fmaxf(mx.w, lrelu(ss.w + sd.w));
    }
#pragma unroll
    for (int o = 16; o; o >>= 1) {
        mx.x = fmaxf(mx.x, __shfl_xor_sync(0xFFFFFFFFu, mx.x, o));
        mx.y = fmaxf(mx.y, __shfl_xor_sync(0xFFFFFFFFu, mx.y, o));
        mx.z = fmaxf(mx.z, __shfl_xor_sync(0xFFFFFFFFu, mx.z, o));
        mx.w = fmaxf(mx.w, __shfl_xor_sync(0xFFFFFFFFu, mx.w, o));
    }

    // pass 2: exp weights (staged in smem) + weighted gather-accumulate
    float4 zv = make_float4(0.f, 0.f, 0.f, 0.f);
    float4 accLo = make_float4(0.f, 0.f, 0.f, 0.f);
    float4 accHi = make_float4(0.f, 0.f, 0.f, 0.f);
    for (int base = rs; base < re; base += 32) {
        int cnt = min(32, re - base);
        int s_l = 0;
        float4 wv = make_float4(0.f, 0.f, 0.f, 0.f);
        if (lane < cnt) {
            s_l = g_csr[base + lane];
            float4 ss = *(const float4*)(g_ssrc1 + s_l * 4);
            wv.x = __expf(lrelu(ss.x + sd.x) - mx.x);
            wv.y = __expf(lrelu(ss.y + sd.y) - mx.y);
            wv.z = __expf(lrelu(ss.z + sd.z) - mx.z);
            wv.w = __expf(lrelu(ss.w + sd.w) - mx.w);
            zv.x += wv.x; zv.y += wv.y; zv.z += wv.z; zv.w += wv.w;
        }
        __syncwarp();
        s_w4[wip][lane] = wv;
        s_si[wip][lane] = s_l;
        __syncwarp();
        for (int t = 0; t < cnt; t++) {
            float4 w4 = s_w4[wip][t];
            int s = s_si[wip][t];
            const float4* hp = (const float4*)(g_h1 + (size_t)s * 256);
            float4 hLo = hp[lane];          // cols lane*4 .. +3     (heads 0/1)
            float4 hHi = hp[32 + lane];     // cols 128+lane*4 ..    (heads 2/3)
            float wa = (lane < 16) ? w4.x : w4.y;
            float wb = (lane < 16) ? w4.z : w4.w;
            accLo.x = fmaf(wa, hLo.x, accLo.x);
            accLo.y = fmaf(wa, hLo.y, accLo.y);
            accLo.z = fmaf(wa, hLo.z, accLo.z);
            accLo.w = fmaf(wa, hLo.w, accLo.w);
            accHi.x = fmaf(wb, hHi.x, accHi.x);
            accHi.y = fmaf(wb, hHi.y, accHi.y);
            accHi.z = fmaf(wb, hHi.z, accHi.z);
            accHi.w = fmaf(wb, hHi.w, accHi.w);
        }
    }
#pragma unroll
    for (int o = 16; o; o >>= 1) {
        zv.x += __shfl_xor_sync(0xFFFFFFFFu, zv.x, o);
        zv.y += __shfl_xor_sync(0xFFFFFFFFu, zv.y, o);
        zv.z += __shfl_xor_sync(0xFFFFFFFFu, zv.z, o);
        zv.w += __shfl_xor_sync(0xFFFFFFFFu, zv.w, o);
    }
    float ia = __fdividef(1.f, ((lane < 16) ? zv.x : zv.y) + EPS);
    float ib = __fdividef(1.f, ((lane < 16) ? zv.z : zv.w) + EPS);
    float4 bLo = *(const float4*)(b1 + lane * 4);
    float4 bHi = *(const float4*)(b1 + 128 + lane * 4);
    float4 v;
    v.x = elu(fmaf(accLo.x, ia, bLo.x));
    v.y = elu(fmaf(accLo.y, ia, bLo.y));
    v.z = elu(fmaf(accLo.z, ia, bLo.z));
    v.w = elu(fmaf(accLo.w, ia, bLo.w));
    *(float4*)(g_out1 + (size_t)wid * 256 + lane * 4) = v;
    v.x = elu(fmaf(accHi.x, ib, bHi.x));
    v.y = elu(fmaf(accHi.y, ib, bHi.y));
    v.z = elu(fmaf(accHi.z, ib, bHi.z));
    v.w = elu(fmaf(accHi.w, ib, bHi.w));
    *(float4*)(g_out1 + (size_t)wid * 256 + 128 + lane * 4) = v;
}

// ---------------- GEMM2 + scores2 fused ----------------
// [50000,256] @ [256,128] f32x2 packed, then per-node per-head half-scores
__global__ void __launch_bounds__(256) k_gemm2s(const float* __restrict__ W2,
                                                const float* __restrict__ a_src2,
                                                const float* __restrict__ a_dst2) {
    __shared__ __align__(16) float sxt[256 * 36];  // [k][m], stride 36 (pad)
    int tid = threadIdx.x;
    int n0 = blockIdx.x * 32;
    int cnt = min(32, NN - n0);
    if (cnt < 32) {
        for (int i = tid; i < 256 * 36; i += 256) sxt[i] = 0.f;
        __syncthreads();
    }
    for (int i = tid; i < cnt * 256; i += 256) {
        int m = i >> 8, k = i & 255;
        sxt[k * 36 + m] = g_out1[(size_t)(n0 + m) * 256 + k];
    }
    __syncthreads();
    int col = tid & 127;
    int g = tid >> 7;                              // node group: g*16 .. g*16+15
    ull acc[8];
#pragma unroll
    for (int p = 0; p < 8; p++) acc[p] = 0ull;
#pragma unroll 4
    for (int k = 0; k < 256; k++) {
        float wv = W2[k * 128 + col];
        ull wp = pack2(wv, wv);
        const ulonglong2* xp = (const ulonglong2*)(sxt + k * 36 + g * 16);
#pragma unroll
        for (int q = 0; q < 4; q++) {
            ulonglong2 xv = xp[q];
            acc[2 * q]     = fma2(xv.x, wp, acc[2 * q]);
            acc[2 * q + 1] = fma2(xv.y, wp, acc[2 * q + 1]);
        }
    }
    __syncthreads();                               // done reading sxt; reuse it
    float* sh2 = sxt;                              // [32][128] h2 tile
#pragma unroll
    for (int p = 0; p < 8; p++) {
        float lo, hi; unpack2(acc[p], lo, hi);
        int m = g * 16 + 2 * p;
        if (m < cnt)     g_h2[(size_t)(n0 + m) * 128 + col] = lo;
        if (m + 1 < cnt) g_h2[(size_t)(n0 + m + 1) * 128 + col] = hi;
        sh2[m * 128 + col] = lo;
        sh2[(m + 1) * 128 + col] = hi;
    }
    __syncthreads();

    // scores: 8 warps x 4 nodes. lane handles cols lane*4..+3.
    // head = lane<16 ? 0 : 1; reduce within 16-lane halves.
    int wrp = tid >> 5, lane = tid & 31;
    float4 sA = ((const float4*)a_src2)[lane];
    float4 dA = ((const float4*)a_dst2)[lane];
#pragma unroll
    for (int mi = 0; mi < 4; mi++) {
        int m = wrp * 4 + mi;
        float4 h = ((const float4*)(sh2 + m * 128))[lane];
        float ps = h.x * sA.x + h.y * sA.y + h.z * sA.z + h.w * sA.w;
        float pd = h.x * dA.x + h.y * dA.y + h.z * dA.z + h.w * dA.w;
#pragma unroll
        for (int o = 8; o; o >>= 1) {
            ps += __shfl_down_sync(0xFFFFFFFFu, ps, o);
            pd += __shfl_down_sync(0xFFFFFFFFu, pd, o);
        }
        int n = n0 + m;
        if (m < cnt) {
            if (lane == 0)  { g_ssrc2[n * 2 + 0] = ps; g_sdst2[n * 2 + 0] = pd; }
            if (lane == 16) { g_ssrc2[n * 2 + 1] = ps; g_sdst2[n * 2 + 1] = pd; }
        }
    }
}

// ---------------- layer-2 aggregation + FC + sigmoid, warp / dst -------------
// also re-zeroes g_deg / g_pub for the next replay
__global__ void __launch_bounds__(256) k_agg2(const float* __restrict__ b2,
                                              const float* __restrict__ Wfc,
                                              const float* __restrict__ bfc,
                                              float* __restrict__ out) {
    __shared__ __align__(8) float2 s_w2[8][32];
    __shared__ int s_si[8][32];
    int t0 = blockIdx.x * blockDim.x + threadIdx.x;
    if (t0 < NN) g_deg[t0] = 0;          // restore invariant for next call
    if (t0 < NBLK) g_pub[t0] = 0;

    int wid = t0 >> 5;
    if (wid >= NN) return;
    int wip = threadIdx.x >> 5;
    int lane = threadIdx.x & 31;
    int rs = g_rs[wid], re = g_rs[wid + 1];
    float2 sd = *(const float2*)(g_sdst2 + wid * 2);

    float2 mx = make_float2(-3.4e38f, -3.4e38f);
    for (int j = rs + lane; j < re; j += 32) {
        int s = g_csr[j];
        float2 ss = *(const float2*)(g_ssrc2 + s * 2);
        mx.x = fmaxf(mx.x, lrelu(ss.x + sd.x));
        mx.y = fmaxf(mx.y, lrelu(ss.y + sd.y));
    }
#pragma unroll
    for (int o = 16; o; o >>= 1) {
        mx.x = fmaxf(mx.x, __shfl_xor_sync(0xFFFFFFFFu, mx.x, o));
        mx.y = fmaxf(mx.y, __shfl_xor_sync(0xFFFFFFFFu, mx.y, o));
    }

    float2 zv = make_float2(0.f, 0.f);
    float4 acc = make_float4(0.f, 0.f, 0.f, 0.f);
    for (int base = rs; base < re; base += 32) {
        int cnt = min(32, re - base);
        int s_l = 0;
        float2 wv = make_float2(0.f, 0.f);
        if (lane < cnt) {
            s_l = g_csr[base + lane];
            float2 ss = *(const float2*)(g_ssrc2 + s_l * 2);
            wv.x = __expf(lrelu(ss.x + sd.x) - mx.x);
            wv.y = __expf(lrelu(ss.y + sd.y) - mx.y);
            zv.x += wv.x; zv.y += wv.y;
        }
        __syncwarp();
        s_w2[wip][lane] = wv;
        s_si[wip][lane] = s_l;
        __syncwarp();
        for (int t = 0; t < cnt; t++) {
            float2 w2 = s_w2[wip][t];
            int s = s_si[wip][t];
            const float4* hp = (const float4*)(g_h2 + (size_t)s * 128);
            float4 h = hp[lane];            // cols lane*4 .. +3
            float wa = (lane < 16) ? w2.x : w2.y;
            acc.x = fmaf(wa, h.x, acc.x);
            acc.y = fmaf(wa, h.y, acc.y);
            acc.z = fmaf(wa, h.z, acc.z);
            acc.w = fmaf(wa, h.w, acc.w);
        }
    }
#pragma unroll
    for (int o = 16; o; o >>= 1) {
        zv.x += __shfl_xor_sync(0xFFFFFFFFu, zv.x, o);
        zv.y += __shfl_xor_sync(0xFFFFFFFFu, zv.y, o);
    }
    float iz = __fdividef(1.f, ((lane < 16) ? zv.x : zv.y) + EPS);
    float4 b = *(const float4*)(b2 + lane * 4);
    float4 wf = *(const float4*)(Wfc + lane * 4);
    float t = elu(fmaf(acc.x, iz, b.x)) * wf.x
            + elu(fmaf(acc.y, iz, b.y)) * wf.y
            + elu(fmaf(acc.z, iz, b.z)) * wf.z
            + elu(fmaf(acc.w, iz, b.w)) * wf.w;
#pragma unroll
    for (int o = 16; o; o >>= 1) t += __shfl_down_sync(0xFFFFFFFFu, t, o);
    if (lane == 0) {
        float s = t + bfc[0];
        out[wid] = __fdividef(1.f, 1.f + __expf(-s));
    }
}

// ---------------- launch ----------------
extern "C" void kernel_launch(void* const* d_in, const int* in_sizes, int n_in,
                              void* d_out, int out_size) {
    const float* x      = (const float*)d_in[0];
    const void*  ei     = d_in[1];
    const float* W1     = (const float*)d_in[2];
    const float* a_src1 = (const float*)d_in[3];
    const float* a_dst1 = (const float*)d_in[4];
    const float* b1     = (const float*)d_in[5];
    const float* W2     = (const float*)d_in[6];
    const float* a_src2 = (const float*)d_in[7];
    const float* a_dst2 = (const float*)d_in[8];
    const float* b2     = (const float*)d_in[9];
    const float* Wfc    = (const float*)d_in[10];
    const float* bfc    = (const float*)d_in[11];
    float* out = (float*)d_out;

    k_conv_gemm1s<<<NCONV + NN / 16, 256>>>(ei, x, W1, a_src1, a_dst1); // 0
    k_scan<<<NBLK, SCAN_B>>>();                                        // 1
    k_scatter<<<(ETOT + 255) / 256, 256>>>();                          // 2
    k_agg1<<<(NN + 7) / 8, 256>>>(b1);                                 // 3 <- ncu
    k_gemm2s<<<(NN + 31) / 32, 256>>>(W2, a_src2, a_dst2);             // 4
    k_agg2<<<(NN + 7) / 8, 256>>>(b2, Wfc, bfc, out);                  // 5
}